// round 12
// baseline (speedup 1.0000x reference)
#include <cuda_runtime.h>
#include <cuda_bf16.h>
#include <math.h>

// Problem constants
#define BB 4
#define CC 512
#define LL 2048
#define HH 8
#define DHD 64
#define BLT (BB * LL)          // 8192
#define N_QKV (3 * CC)         // 1536
#define EPSV 1e-5f
#define SCALEV 0.125f          // 64^-0.5
#define LOG2E 1.4426950408889634f

#define PERM16(x) ((((x) & 3) << 2) | ((x) >> 2))
// pair-block perm within each 16: local pair pr=(d>>1)&7 -> 4*(pr&3)+2*(pr>>2)+odd
#define PPERM(d) (((d) & ~15) | (((((d) >> 1) & 3)) << 2) | (((((d) >> 1) & 7) >> 2) << 1) | ((d) & 1))

// Scratch (device globals; allocation-free contract)
__device__ float g_qkv[(size_t)BLT * N_QKV];       // Q region used (natural layout)
__device__ float g_xt[(size_t)BLT * CC];           // x transposed [bl][c], PERM16 cols
__device__ __nv_bfloat16 g_ktb[(size_t)BB * HH * LL * DHD]; // K bf16 [(b,h),token,dh_pi]
__device__ __nv_bfloat16 g_vtb[(size_t)BB * HH * DHD * LL]; // V^T bf16, token pair-permuted
__device__ float g_o[(size_t)BLT * CC];            // attn out, [bl, C] k-permuted cols
__device__ float g_wqkvp[(size_t)N_QKV * CC];      // gamma .* w_qkv, k-permuted
__device__ float g_wprojp[(size_t)CC * CC];        // w_proj, k-permuted
__device__ float g_mu[BLT];                        // LN mean per row
__device__ float g_rs[BLT];                        // LN rstd per row
__device__ float g_cs[N_QKV];                      // colsum of gamma.*w_qkv
__device__ float g_be[N_QKV];                      // b_qkv + beta . w_qkv

// ---------------------------------------------------------------------------
// helpers
// ---------------------------------------------------------------------------
__device__ __forceinline__ void mma_tf32(float c[4], const unsigned a[4],
                                         unsigned b0, unsigned b1) {
    asm volatile(
        "mma.sync.aligned.m16n8k8.row.col.f32.tf32.tf32.f32 "
        "{%0,%1,%2,%3}, {%4,%5,%6,%7}, {%8,%9}, {%0,%1,%2,%3};"
        : "+f"(c[0]), "+f"(c[1]), "+f"(c[2]), "+f"(c[3])
        : "r"(a[0]), "r"(a[1]), "r"(a[2]), "r"(a[3]), "r"(b0), "r"(b1));
}

__device__ __forceinline__ void mma_bf16(float c[4], const unsigned a[4],
                                         unsigned b0, unsigned b1) {
    asm volatile(
        "mma.sync.aligned.m16n8k16.row.col.f32.bf16.bf16.f32 "
        "{%0,%1,%2,%3}, {%4,%5,%6,%7}, {%8,%9}, {%0,%1,%2,%3};"
        : "+f"(c[0]), "+f"(c[1]), "+f"(c[2]), "+f"(c[3])
        : "r"(a[0]), "r"(a[1]), "r"(a[2]), "r"(a[3]), "r"(b0), "r"(b1));
}

__device__ __forceinline__ unsigned packbf(float hi, float lo) {
    unsigned r;
    asm("cvt.rn.bf16x2.f32 %0, %1, %2;" : "=r"(r) : "f"(hi), "f"(lo));
    return r;
}

__device__ __forceinline__ void cpa16(unsigned s, const void* g) {
    asm volatile("cp.async.cg.shared.global [%0], [%1], 16;" :: "r"(s), "l"(g));
}
#define CPA_COMMIT() asm volatile("cp.async.commit_group;")
#define CPA_WAIT(n)  asm volatile("cp.async.wait_group %0;" :: "n"(n))

// ---------------------------------------------------------------------------
// Kernel 1: LN stats + transpose. mu/rstd per (b,l); also writes
// g_xt[bl][c] = x[b,c,l] with PERM16 applied within each 16-c group.
// Block: 256 thr, 64 l-positions. 8 chunks of 64 c.
// ---------------------------------------------------------------------------
__global__ __launch_bounds__(256) void lnx_kernel(const float* __restrict__ x)
{
    __shared__ float tile[64][65];
    __shared__ float rsum[4][64], rsq[4][64];

    const int tid = threadIdx.x;
    const int l0 = blockIdx.x * 64;
    const int b = blockIdx.y;
    const int lw = tid & 63;
    const int cg = tid >> 6;

    float sum = 0.f, sq = 0.f;

    for (int ch = 0; ch < 8; ch++) {
        // load 64c x 64l tile, coalesced float4
        #pragma unroll
        for (int r = 0; r < 4; r++) {
            int idx = tid + r * 256;       // (c', f4): 64 x 16
            int cp = idx >> 4, f4 = idx & 15;
            float4 v = *(const float4*)&x[((size_t)(b * CC + ch * 64 + cp)) * LL + l0 + f4 * 4];
            tile[cp][f4 * 4 + 0] = v.x;
            tile[cp][f4 * 4 + 1] = v.y;
            tile[cp][f4 * 4 + 2] = v.z;
            tile[cp][f4 * 4 + 3] = v.w;
        }
        __syncthreads();

        // stats accumulate + transposed permuted write
        size_t orow = (size_t)(b * LL + l0 + lw) * CC + ch * 64 + cg * 16;
        #pragma unroll
        for (int i = 0; i < 16; i++) {
            float v = tile[cg * 16 + i][lw];
            sum += v;
            sq += v * v;
            g_xt[orow + PERM16(i)] = v;
        }
        __syncthreads();
    }

    rsum[cg][lw] = sum;
    rsq[cg][lw] = sq;
    __syncthreads();
    if (cg == 0) {
        float ts = rsum[0][lw] + rsum[1][lw] + rsum[2][lw] + rsum[3][lw];
        float tq = rsq[0][lw] + rsq[1][lw] + rsq[2][lw] + rsq[3][lw];
        float mean = ts * (1.0f / CC);
        float var = tq * (1.0f / CC) - mean * mean;
        g_mu[b * LL + l0 + lw] = mean;
        g_rs[b * LL + l0 + lw] = rsqrtf(var + EPSV);
    }
}

// ---------------------------------------------------------------------------
// Kernel 2: weight prep (unchanged).
// ---------------------------------------------------------------------------
__global__ __launch_bounds__(128) void prep_kernel(
    const float* __restrict__ w_qkv, const float* __restrict__ b_qkv,
    const float* __restrict__ gamma, const float* __restrict__ beta,
    const float* __restrict__ w_proj)
{
    const int n = blockIdx.x;
    const int t = threadIdx.x;
    if (n < N_QKV) {
        const float* wr = w_qkv + (size_t)n * CC;
        float gs = 0.f, bs = 0.f;
        #pragma unroll
        for (int j = 0; j < 4; j++) {
            int k = j * 128 + t;
            float w = wr[k];
            float v = __ldg(&gamma[k]) * w;
            gs += v;
            bs += __ldg(&beta[k]) * w;
            int kp = (k & ~15) | PERM16(k & 15);
            g_wqkvp[(size_t)n * CC + kp] = v;
        }
        __shared__ float sg[128], sb[128];
        sg[t] = gs; sb[t] = bs;
        __syncthreads();
        for (int off = 64; off > 0; off >>= 1) {
            if (t < off) { sg[t] += sg[t + off]; sb[t] += sb[t + off]; }
            __syncthreads();
        }
        if (t == 0) {
            g_cs[n] = sg[0];
            g_be[n] = sb[0] + b_qkv[n];
        }
    } else {
        const int r = n - N_QKV;
        #pragma unroll
        for (int j = 0; j < 4; j++) {
            int k = j * 128 + t;
            int kp = (k & ~15) | PERM16(k & 15);
            g_wprojp[(size_t)r * CC + kp] = w_proj[(size_t)r * CC + k];
        }
    }
}

// ---------------------------------------------------------------------------
// Kernel 3: QKV GEMM (proj-style vectorized fragments from g_xt),
// fused LN affine epilogue.
// Q region: natural fp32 in g_qkv.
// K region: bf16 to g_ktb[(b,h)][token][dh pair-permuted].
// V region: bf16 TRANSPOSED to g_vtb[(b,h)][dh][token pair-permuted].
// ---------------------------------------------------------------------------
#define QA_W 2048            // 128*16
#define QB_W 2048            // 128*16
#define QSTG (QA_W + QB_W)   // 4096
#define QSMEM (QSTG * 4 * 4) // 65536 B

__global__ __launch_bounds__(256, 2) void qkv_gemm()
{
    extern __shared__ unsigned smg[];
    const int m0 = blockIdx.x * 128;
    const int n0 = blockIdx.y * 128;
    const int b = m0 >> 11;
    const int l0 = m0 & (LL - 1);

    const int tid = threadIdx.x;
    const int warp = tid >> 5;
    const int lane = tid & 31;
    const int qr = lane >> 2;
    const int qc = lane & 3;
    const int wm = (warp >> 2) * 64;
    const int wn = (warp & 3) * 32;

    unsigned sbase = (unsigned)__cvta_generic_to_shared(smg);

    auto issue_stage = [&](int kk0, int s) {
        unsigned st = sbase + (unsigned)(s * QSTG) * 4u;
        #pragma unroll
        for (int it = 0; it < 2; it++) {
            int idx = tid + it * 256;        // (m, k4): 128 x 4
            int m = idx >> 2, k4 = idx & 3;
            cpa16(st + (unsigned)(m * 16 + k4 * 4) * 4u,
                  &g_xt[(size_t)(m0 + m) * CC + kk0 + k4 * 4]);
        }
        unsigned bt = st + (unsigned)QA_W * 4u;
        #pragma unroll
        for (int it = 0; it < 2; it++) {
            int idx = tid + it * 256;        // (n, k4): 128 x 4
            int n = idx >> 2, k4 = idx & 3;
            cpa16(bt + (unsigned)(n * 16 + k4 * 4) * 4u,
                  &g_wqkvp[(size_t)(n0 + n) * CC + kk0 + k4 * 4]);
        }
    };

    float acc[4][4][4];
    #pragma unroll
    for (int i = 0; i < 4; i++)
        #pragma unroll
        for (int j = 0; j < 4; j++)
            #pragma unroll
            for (int r = 0; r < 4; r++) acc[i][j][r] = 0.f;

    issue_stage(0, 0);  CPA_COMMIT();
    issue_stage(16, 1); CPA_COMMIT();
    issue_stage(32, 2); CPA_COMMIT();

    for (int kt = 0; kt < 32; kt++) {
        CPA_WAIT(2);
        __syncthreads();
        if (kt + 3 < 32) issue_stage((kt + 3) * 16, (kt + 3) & 3);
        CPA_COMMIT();

        const unsigned* As_ = smg + (kt & 3) * QSTG;
        const unsigned* Bs_ = As_ + QA_W;

        uint4 bq[4];
        #pragma unroll
        for (int nt = 0; nt < 4; nt++)
            bq[nt] = *(const uint4*)&Bs_[(wn + nt * 8 + qr) * 16 + 4 * qc];

        #pragma unroll
        for (int mt = 0; mt < 4; mt++) {
            int mb = wm + mt * 16;
            uint4 a0 = *(const uint4*)&As_[(mb + qr) * 16 + 4 * qc];
            uint4 a1 = *(const uint4*)&As_[(mb + qr + 8) * 16 + 4 * qc];
            unsigned af0[4] = {a0.x, a1.x, a0.y, a1.y};
            unsigned af1[4] = {a0.z, a1.z, a0.w, a1.w};
            #pragma unroll
            for (int nt = 0; nt < 4; nt++) {
                mma_tf32(acc[mt][nt], af0, bq[nt].x, bq[nt].y);
                mma_tf32(acc[mt][nt], af1, bq[nt].z, bq[nt].w);
            }
        }
    }

    // epilogue: LN affine fold; K -> g_ktb (bf16 pairs); V -> g_vtb (bf16)
    const bool kreg = (n0 >= CC && n0 < 2 * CC);
    const bool vreg = (n0 >= 2 * CC);
    const int tpo0 = (qr >> 1) * 4 + (qr & 1);   // pi(qr), tokens 0-7
    const int tpo1 = tpo0 + 2;                   // pi(qr+8)
    #pragma unroll
    for (int mt = 0; mt < 4; mt++) {
        int ml0 = wm + mt * 16 + qr;
        int ml1 = ml0 + 8;
        float s0 = g_rs[m0 + ml0], u0 = g_mu[m0 + ml0];
        float s1 = g_rs[m0 + ml1], u1 = g_mu[m0 + ml1];
        #pragma unroll
        for (int nt = 0; nt < 4; nt++) {
            int n = n0 + wn + nt * 8 + 2 * qc;
            float cs0 = __ldg(&g_cs[n]),     be0 = __ldg(&g_be[n]);
            float cs1 = __ldg(&g_cs[n + 1]), be1 = __ldg(&g_be[n + 1]);
            float v00 = s0 * (acc[mt][nt][0] - u0 * cs0) + be0;
            float v01 = s0 * (acc[mt][nt][1] - u0 * cs1) + be1;
            float v10 = s1 * (acc[mt][nt][2] - u1 * cs0) + be0;
            float v11 = s1 * (acc[mt][nt][3] - u1 * cs1) + be1;
            if (vreg) {
                int hh = (n - 2 * CC) >> 6;
                int dh = (n - 2 * CC) & 63;
                int tq = l0 + wm + mt * 16;            // 16-aligned token base
                size_t vb = ((size_t)(b * HH + hh) * DHD + dh) * LL;
                g_vtb[vb + tq + tpo0]      = __float2bfloat16(v00);
                g_vtb[vb + LL + tq + tpo0] = __float2bfloat16(v01);
                g_vtb[vb + tq + tpo1]      = __float2bfloat16(v10);
                g_vtb[vb + LL + tq + tpo1] = __float2bfloat16(v11);
            } else if (kreg) {
                int dh = (n - CC) & 63;                // even
                int hh = (n - CC) >> 6;
                int np = PPERM(dh);                    // even; pair -> np, np+1
                int tok0 = l0 + ml0;
                int tok1 = l0 + ml1;
                size_t kbase = ((size_t)(b * HH + hh) * LL);
                *(unsigned*)&g_ktb[(kbase + tok0) * DHD + np] = packbf(v01, v00);
                *(unsigned*)&g_ktb[(kbase + tok1) * DHD + np] = packbf(v11, v10);
            } else {
                *(float2*)&g_qkv[(size_t)(m0 + ml0) * N_QKV + n] = make_float2(v00, v01);
                *(float2*)&g_qkv[(size_t)(m0 + ml1) * N_QKV + n] = make_float2(v10, v11);
            }
        }
    }
}

// ---------------------------------------------------------------------------
// Kernel 5: proj GEMM + bias + residual (unchanged).
// ---------------------------------------------------------------------------
#define PA_W 2048
#define PB_W 2048
#define PSTG (PA_W + PB_W)   // 4096
#define PSMEM (PSTG * 4 * 4) // 65536 B

__global__ __launch_bounds__(256, 2) void proj_gemm(
    const float* __restrict__ bias,
    const float* __restrict__ xres,
    float* __restrict__ Cout)
{
    extern __shared__ unsigned smg[];
    const int m0 = blockIdx.x * 128;
    const int n0 = blockIdx.y * 128;
    const int b = m0 >> 11;
    const int l0 = m0 & (LL - 1);

    const int tid = threadIdx.x;
    const int warp = tid >> 5;
    const int lane = tid & 31;
    const int qr = lane >> 2;
    const int qc = lane & 3;
    const int wm = (warp >> 2) * 64;
    const int wn = (warp & 3) * 32;

    unsigned sbase = (unsigned)__cvta_generic_to_shared(smg);

    auto issue_stage = [&](int kk0, int s) {
        unsigned st = sbase + (unsigned)(s * PSTG) * 4u;
        #pragma unroll
        for (int it = 0; it < 2; it++) {
            int idx = tid + it * 256;
            int m = idx >> 2, k4 = idx & 3;
            cpa16(st + (unsigned)(m * 16 + k4 * 4) * 4u,
                  &g_o[(size_t)(m0 + m) * CC + kk0 + k4 * 4]);
        }
        unsigned bt = st + (unsigned)PA_W * 4u;
        #pragma unroll
        for (int it = 0; it < 2; it++) {
            int idx = tid + it * 256;
            int n = idx >> 2, k4 = idx & 3;
            cpa16(bt + (unsigned)(n * 16 + k4 * 4) * 4u,
                  &g_wprojp[(size_t)(n0 + n) * CC + kk0 + k4 * 4]);
        }
    };

    float acc[4][4][4];
    #pragma unroll
    for (int i = 0; i < 4; i++)
        #pragma unroll
        for (int j = 0; j < 4; j++)
            #pragma unroll
            for (int r = 0; r < 4; r++) acc[i][j][r] = 0.f;

    issue_stage(0, 0);  CPA_COMMIT();
    issue_stage(16, 1); CPA_COMMIT();
    issue_stage(32, 2); CPA_COMMIT();

    for (int kt = 0; kt < 32; kt++) {
        CPA_WAIT(2);
        __syncthreads();
        if (kt + 3 < 32) issue_stage((kt + 3) * 16, (kt + 3) & 3);
        CPA_COMMIT();

        const unsigned* As_ = smg + (kt & 3) * PSTG;
        const unsigned* Bs_ = As_ + PA_W;

        uint4 bq[4];
        #pragma unroll
        for (int nt = 0; nt < 4; nt++)
            bq[nt] = *(const uint4*)&Bs_[(wn + nt * 8 + qr) * 16 + 4 * qc];

        #pragma unroll
        for (int mt = 0; mt < 4; mt++) {
            int mb = wm + mt * 16;
            uint4 a0 = *(const uint4*)&As_[(mb + qr) * 16 + 4 * qc];
            uint4 a1 = *(const uint4*)&As_[(mb + qr + 8) * 16 + 4 * qc];
            unsigned af0[4] = {a0.x, a1.x, a0.y, a1.y};
            unsigned af1[4] = {a0.z, a1.z, a0.w, a1.w};
            #pragma unroll
            for (int nt = 0; nt < 4; nt++) {
                mma_tf32(acc[mt][nt], af0, bq[nt].x, bq[nt].y);
                mma_tf32(acc[mt][nt], af1, bq[nt].z, bq[nt].w);
            }
        }
    }

    #pragma unroll
    for (int mt = 0; mt < 4; mt++) {
        #pragma unroll
        for (int nt = 0; nt < 4; nt++) {
            int n = n0 + wn + nt * 8 + 2 * qc;
            float b0v = __ldg(&bias[n]);
            float b1v = __ldg(&bias[n + 1]);
            int ml0 = wm + mt * 16 + qr;
            size_t a00 = ((size_t)(b * CC + n)) * LL + l0 + ml0;
            size_t a01 = ((size_t)(b * CC + n + 1)) * LL + l0 + ml0;
            Cout[a00]     = acc[mt][nt][0] + b0v + xres[a00];
            Cout[a01]     = acc[mt][nt][1] + b1v + xres[a01];
            Cout[a00 + 8] = acc[mt][nt][2] + b0v + xres[a00 + 8];
            Cout[a01 + 8] = acc[mt][nt][3] + b1v + xres[a01 + 8];
        }
    }
}

// ---------------------------------------------------------------------------
// Kernel 4: flash attention, all-bf16 MMA. 4 warps/CTA, 4 CTAs/SM.
// K AND V double-buffered -> ONE __syncthreads per tile; both prefetched
// at tile top (no load serialized behind S).
// smem (words): K0 2560 @0, K1 @2560, V0 @5120, V1 @7680. 40960 B.
// ---------------------------------------------------------------------------
#define KSTB 80              // bf16 units per K row
#define VTSTB 80             // bf16 units per Vt row
#define AT_K0W 0
#define AT_K1W 2560
#define AT_V0W 5120
#define AT_V1W 7680
#define AT_SMEM_BYTES (10240 * 4)
#define NT (LL / 64)

__global__ __launch_bounds__(128, 4) void attn_mma()
{
    extern __shared__ unsigned sma[];

    const int q0 = blockIdx.x * 64;
    const int h = blockIdx.y;
    const int b = blockIdx.z;

    const int tid = threadIdx.x;
    const int warp = tid >> 5;
    const int lane = tid & 31;
    const int qr = lane >> 2;
    const int qc = lane & 3;
    const int wrow = warp * 16;

    unsigned sbase = (unsigned)__cvta_generic_to_shared(sma);

    const __nv_bfloat16* kb = g_ktb + (size_t)(b * HH + h) * LL * DHD;
    const __nv_bfloat16* vt = g_vtb + (size_t)(b * HH + h) * DHD * LL;

    auto load_K = [&](int kt) {
        unsigned kd = sbase + (unsigned)((kt & 1) ? AT_K1W : AT_K0W) * 4u;
        #pragma unroll
        for (int it = 0; it < 4; it++) {
            int idx = tid + it * 128;      // (j, c8): 64 x 8 chunks of 16B
            int j = idx >> 3, c8 = idx & 7;
            cpa16(kd + (unsigned)(j * KSTB * 2 + c8 * 16),
                  kb + (size_t)(kt * 64 + j) * DHD + c8 * 8);
        }
    };
    auto load_V = [&](int kt) {
        unsigned vd = sbase + (unsigned)((kt & 1) ? AT_V1W : AT_V0W) * 4u;
        #pragma unroll
        for (int it = 0; it < 4; it++) {
            int idx = tid + it * 128;      // (dh, c8): 64 x 8 chunks of 16B
            int dh = idx >> 3, c8 = idx & 7;
            cpa16(vd + (unsigned)(dh * VTSTB * 2 + c8 * 16),
                  vt + (size_t)dh * LL + kt * 64 + c8 * 8);
        }
    };

    load_K(0);
    load_V(0);
    CPA_COMMIT();

    // Q fragments: bf16x2 packed, scaled by SCALE*log2e (Q region natural fp32)
    const float* qptr = g_qkv + ((size_t)(b * LL + q0 + wrow)) * N_QKV + h * DHD;
    const float qsc = SCALEV * LOG2E;
    unsigned qa[4][4];
    #pragma unroll
    for (int g = 0; g < 4; g++) {
        int k0 = g * 16 + 2 * qc;
        qa[g][0] = packbf(qptr[(size_t)qr * N_QKV + k0 + 1] * qsc,
                          qptr[(size_t)qr * N_QKV + k0] * qsc);
        qa[g][1] = packbf(qptr[(size_t)(qr + 8) * N_QKV + k0 + 1] * qsc,
                          qptr[(size_t)(qr + 8) * N_QKV + k0] * qsc);
        qa[g][2] = packbf(qptr[(size_t)qr * N_QKV + k0 + 9] * qsc,
                          qptr[(size_t)qr * N_QKV + k0 + 8] * qsc);
        qa[g][3] = packbf(qptr[(size_t)(qr + 8) * N_QKV + k0 + 9] * qsc,
                          qptr[(size_t)(qr + 8) * N_QKV + k0 + 8] * qsc);
    }

    float oacc[8][4];
    #pragma unroll
    for (int nt = 0; nt < 8; nt++)
        #pragma unroll
        for (int r = 0; r < 4; r++) oacc[nt][r] = 0.f;
    float lp0 = 0.f, lp1 = 0.f;

    for (int kt = 0; kt < NT; kt++) {
        CPA_WAIT(0);
        __syncthreads();
        if (kt + 1 < NT) { load_K(kt + 1); load_V(kt + 1); }
        CPA_COMMIT();

        const unsigned short* Ks_ =
            (const unsigned short*)(sma + ((kt & 1) ? AT_K1W : AT_K0W));
        const unsigned short* Vt_ =
            (const unsigned short*)(sma + ((kt & 1) ? AT_V1W : AT_V0W));

        // ---- S = (Q*scale*log2e) K^T : bf16 m16n8k16, LDS.64 K frags ----
        float sacc[8][4];
        #pragma unroll
        for (int nt = 0; nt < 8; nt++) {
            #pragma unroll
            for (int r = 0; r < 4; r++) sacc[nt][r] = 0.f;
            #pragma unroll
            for (int g = 0; g < 4; g++) {
                uint2 kv = *(const uint2*)&Ks_[(nt * 8 + qr) * KSTB + g * 16 + qc * 4];
                mma_bf16(sacc[nt], qa[g], kv.x, kv.y);
            }
        }

        // ---- softmax numerator: exp2 directly ----
        #pragma unroll
        for (int nt = 0; nt < 8; nt++) {
            sacc[nt][0] = exp2f(sacc[nt][0]);
            sacc[nt][1] = exp2f(sacc[nt][1]);
            sacc[nt][2] = exp2f(sacc[nt][2]);
            sacc[nt][3] = exp2f(sacc[nt][3]);
            lp0 += sacc[nt][0] + sacc[nt][1];
            lp1 += sacc[nt][2] + sacc[nt][3];
        }

        // ---- O += P V : bf16 m16n8k16, LDS.64 Vt fragments ----
        #pragma unroll
        for (int g = 0; g < 4; g++) {     // 16-key groups
            unsigned pa[4];
            pa[0] = packbf(sacc[2 * g][1],     sacc[2 * g][0]);
            pa[1] = packbf(sacc[2 * g][3],     sacc[2 * g][2]);
            pa[2] = packbf(sacc[2 * g + 1][1], sacc[2 * g + 1][0]);
            pa[3] = packbf(sacc[2 * g + 1][3], sacc[2 * g + 1][2]);
            #pragma unroll
            for (int nt = 0; nt < 8; nt++) {
                uint2 bb = *(const uint2*)&Vt_[(nt * 8 + qr) * VTSTB + g * 16 + qc * 4];
                mma_bf16(oacc[nt], pa, bb.x, bb.y);
            }
        }
    }

    // final sum reduction, normalize, store (k-permuted cols)
    lp0 += __shfl_xor_sync(0xffffffffu, lp0, 1);
    lp0 += __shfl_xor_sync(0xffffffffu, lp0, 2);
    lp1 += __shfl_xor_sync(0xffffffffu, lp1, 1);
    lp1 += __shfl_xor_sync(0xffffffffu, lp1, 2);
    float inv0 = 1.0f / lp0;
    float inv1 = 1.0f / lp1;

    size_t row0 = ((size_t)(b * LL + q0 + wrow + qr)) * CC;
    size_t row1 = row0 + (size_t)8 * CC;
    #pragma unroll
    for (int nt = 0; nt < 8; nt++) {
        int c0 = h * DHD + nt * 8 + 2 * qc;
        int cp0 = (c0 & ~15) | PERM16(c0 & 15);
        int cp1 = cp0 + 4;   // perm(c0+1) = perm(c0)+4 for even c0
        g_o[row0 + cp0] = oacc[nt][0] * inv0;
        g_o[row0 + cp1] = oacc[nt][1] * inv0;
        g_o[row1 + cp0] = oacc[nt][2] * inv1;
        g_o[row1 + cp1] = oacc[nt][3] * inv1;
    }
}

// ---------------------------------------------------------------------------
extern "C" void kernel_launch(void* const* d_in, const int* in_sizes, int n_in,
                              void* d_out, int out_size)
{
    const float* x        = (const float*)d_in[0];
    const float* ln_gamma = (const float*)d_in[1];
    const float* ln_beta  = (const float*)d_in[2];
    const float* w_qkv    = (const float*)d_in[3];
    const float* b_qkv    = (const float*)d_in[4];
    const float* w_proj   = (const float*)d_in[5];
    const float* b_proj   = (const float*)d_in[6];
    float* out = (float*)d_out;

    static int attrs_set = 0;
    if (!attrs_set) {
        cudaFuncSetAttribute(attn_mma, cudaFuncAttributeMaxDynamicSharedMemorySize, AT_SMEM_BYTES);
        cudaFuncSetAttribute(qkv_gemm, cudaFuncAttributeMaxDynamicSharedMemorySize, QSMEM);
        cudaFuncSetAttribute(proj_gemm, cudaFuncAttributeMaxDynamicSharedMemorySize, PSMEM);
        attrs_set = 1;
    }

    // 1. LN stats + x transpose (PERM16'd k-major copy for the QKV GEMM)
    lnx_kernel<<<dim3(LL / 64, BB), 256>>>(x);

    // 2. Weight prep (gamma-fold + k-permutation + colsums)
    prep_kernel<<<N_QKV + CC, 128>>>(w_qkv, b_qkv, ln_gamma, ln_beta, w_proj);

    // 3. QKV GEMM (vectorized frags; LN fused; K -> g_ktb; V -> g_vtb)
    qkv_gemm<<<dim3(BLT / 128, N_QKV / 128), 256, QSMEM>>>();

    // 4. Attention (bf16 S + bf16 PV, K+V double-buffered, 1 sync/tile)
    attn_mma<<<dim3(LL / 64, HH, BB), 128, AT_SMEM_BYTES>>>();

    // 5. Proj GEMM + bias + residual
    proj_gemm<<<dim3(BLT / 128, CC / 128), 256, PSMEM>>>(b_proj, x, out);
}

// round 13
// speedup vs baseline: 1.0928x; 1.0928x over previous
#include <cuda_runtime.h>
#include <cuda_bf16.h>
#include <math.h>

// Problem constants
#define BB 4
#define CC 512
#define LL 2048
#define HH 8
#define DHD 64
#define BLT (BB * LL)          // 8192
#define N_QKV (3 * CC)         // 1536
#define EPSV 1e-5f
#define SCALEV 0.125f          // 64^-0.5
#define LOG2E 1.4426950408889634f

#define PERM16(x) ((((x) & 3) << 2) | ((x) >> 2))
// pair-block perm within each 16: local pair pr=(d>>1)&7 -> 4*(pr&3)+2*(pr>>2)+odd
#define PPERM(d) (((d) & ~15) | (((((d) >> 1) & 3)) << 2) | (((((d) >> 1) & 7) >> 2) << 1) | ((d) & 1))

// Scratch (device globals; allocation-free contract)
__device__ float g_qkv[(size_t)BLT * N_QKV];       // Q region used (natural layout)
__device__ __nv_bfloat16 g_ktb[(size_t)BB * HH * LL * DHD]; // K bf16 [(b,h),token,dh_pi]
__device__ __nv_bfloat16 g_vtb[(size_t)BB * HH * DHD * LL]; // V^T bf16, token pair-permuted
__device__ float g_o[(size_t)BLT * CC];            // attn out, [bl, C] k-permuted cols
__device__ float g_wqkvp[(size_t)N_QKV * CC];      // gamma .* w_qkv, k-permuted
__device__ float g_wprojp[(size_t)CC * CC];        // w_proj, k-permuted
__device__ float g_mu[BLT];                        // LN mean per row
__device__ float g_rs[BLT];                        // LN rstd per row
__device__ float g_cs[N_QKV];                      // colsum of gamma.*w_qkv
__device__ float g_be[N_QKV];                      // b_qkv + beta . w_qkv

// ---------------------------------------------------------------------------
// helpers
// ---------------------------------------------------------------------------
__device__ __forceinline__ void mma_tf32(float c[4], const unsigned a[4],
                                         unsigned b0, unsigned b1) {
    asm volatile(
        "mma.sync.aligned.m16n8k8.row.col.f32.tf32.tf32.f32 "
        "{%0,%1,%2,%3}, {%4,%5,%6,%7}, {%8,%9}, {%0,%1,%2,%3};"
        : "+f"(c[0]), "+f"(c[1]), "+f"(c[2]), "+f"(c[3])
        : "r"(a[0]), "r"(a[1]), "r"(a[2]), "r"(a[3]), "r"(b0), "r"(b1));
}

__device__ __forceinline__ void mma_bf16(float c[4], const unsigned a[4],
                                         unsigned b0, unsigned b1) {
    asm volatile(
        "mma.sync.aligned.m16n8k16.row.col.f32.bf16.bf16.f32 "
        "{%0,%1,%2,%3}, {%4,%5,%6,%7}, {%8,%9}, {%0,%1,%2,%3};"
        : "+f"(c[0]), "+f"(c[1]), "+f"(c[2]), "+f"(c[3])
        : "r"(a[0]), "r"(a[1]), "r"(a[2]), "r"(a[3]), "r"(b0), "r"(b1));
}

__device__ __forceinline__ unsigned packbf(float hi, float lo) {
    unsigned r;
    asm("cvt.rn.bf16x2.f32 %0, %1, %2;" : "=r"(r) : "f"(hi), "f"(lo));
    return r;
}

__device__ __forceinline__ void cpa16(unsigned s, const void* g) {
    asm volatile("cp.async.cg.shared.global [%0], [%1], 16;" :: "r"(s), "l"(g));
}
#define CPA_COMMIT() asm volatile("cp.async.commit_group;")
#define CPA_WAIT(n)  asm volatile("cp.async.wait_group %0;" :: "n"(n))

// ---------------------------------------------------------------------------
// Kernel 1: LN stats only. mu/rstd per (b,l).
// ---------------------------------------------------------------------------
__global__ __launch_bounds__(256) void ln_stats(const float* __restrict__ x)
{
    const int tx = threadIdx.x & 63;
    const int cg = threadIdx.x >> 6;
    const int l = blockIdx.x * 64 + tx;
    const int b = blockIdx.y;
    const size_t base = (size_t)b * CC * LL + l;

    float sum = 0.f, sq = 0.f;
    #pragma unroll 8
    for (int cc = 0; cc < 128; cc++) {
        int c = cg * 128 + cc;
        float v = x[base + (size_t)c * LL];
        sum += v;
        sq += v * v;
    }
    __shared__ float rs[4][64];
    __shared__ float rq[4][64];
    rs[cg][tx] = sum;
    rq[cg][tx] = sq;
    __syncthreads();
    if (cg == 0) {
        float ts = rs[0][tx] + rs[1][tx] + rs[2][tx] + rs[3][tx];
        float tq = rq[0][tx] + rq[1][tx] + rq[2][tx] + rq[3][tx];
        float mean = ts * (1.0f / CC);
        float var = tq * (1.0f / CC) - mean * mean;
        g_mu[b * LL + l] = mean;
        g_rs[b * LL + l] = rsqrtf(var + EPSV);
    }
}

// ---------------------------------------------------------------------------
// Kernel 2: weight prep (unchanged).
// ---------------------------------------------------------------------------
__global__ __launch_bounds__(128) void prep_kernel(
    const float* __restrict__ w_qkv, const float* __restrict__ b_qkv,
    const float* __restrict__ gamma, const float* __restrict__ beta,
    const float* __restrict__ w_proj)
{
    const int n = blockIdx.x;
    const int t = threadIdx.x;
    if (n < N_QKV) {
        const float* wr = w_qkv + (size_t)n * CC;
        float gs = 0.f, bs = 0.f;
        #pragma unroll
        for (int j = 0; j < 4; j++) {
            int k = j * 128 + t;
            float w = wr[k];
            float v = __ldg(&gamma[k]) * w;
            gs += v;
            bs += __ldg(&beta[k]) * w;
            int kp = (k & ~15) | PERM16(k & 15);
            g_wqkvp[(size_t)n * CC + kp] = v;
        }
        __shared__ float sg[128], sb[128];
        sg[t] = gs; sb[t] = bs;
        __syncthreads();
        for (int off = 64; off > 0; off >>= 1) {
            if (t < off) { sg[t] += sg[t + off]; sb[t] += sb[t + off]; }
            __syncthreads();
        }
        if (t == 0) {
            g_cs[n] = sg[0];
            g_be[n] = sb[0] + b_qkv[n];
        }
    } else {
        const int r = n - N_QKV;
        #pragma unroll
        for (int j = 0; j < 4; j++) {
            int k = j * 128 + t;
            int kp = (k & ~15) | PERM16(k & 15);
            g_wprojp[(size_t)r * CC + kp] = w_proj[(size_t)r * CC + k];
        }
    }
}

// ---------------------------------------------------------------------------
// Kernel 3: QKV GEMM (AMAJ: x read m-contiguous from [B,C,L]), fused LN epi.
// Q region: natural fp32 in g_qkv.
// K region: bf16 to g_ktb[(b,h)][token][dh pair-permuted].
// V region: bf16 TRANSPOSED to g_vtb[(b,h)][dh][token pair-permuted].
// ---------------------------------------------------------------------------
#define QA_W 2176            // 16*136
#define QB_W 2048            // 128*16
#define QSTG (QA_W + QB_W)   // 4224
#define QSMEM (QSTG * 4 * 4) // 67584 B

__global__ __launch_bounds__(256, 2) void qkv_gemm(const float* __restrict__ x)
{
    extern __shared__ unsigned smg[];
    const int m0 = blockIdx.x * 128;
    const int n0 = blockIdx.y * 128;
    const int b = m0 >> 11;
    const int l0 = m0 & (LL - 1);

    const int tid = threadIdx.x;
    const int warp = tid >> 5;
    const int lane = tid & 31;
    const int qr = lane >> 2;
    const int qc = lane & 3;
    const int wm = (warp >> 2) * 64;
    const int wn = (warp & 3) * 32;

    unsigned sbase = (unsigned)__cvta_generic_to_shared(smg);

    auto issue_stage = [&](int kk0, int s) {
        unsigned st = sbase + (unsigned)(s * QSTG) * 4u;
        #pragma unroll
        for (int it = 0; it < 2; it++) {
            int idx = tid + it * 256;        // (k, m4): 16 x 32
            int k = idx >> 5, m4 = idx & 31;
            cpa16(st + (unsigned)(k * 136 + m4 * 4) * 4u,
                  &x[((size_t)(b * CC + kk0 + k)) * LL + l0 + m4 * 4]);
        }
        unsigned bt = st + (unsigned)QA_W * 4u;
        #pragma unroll
        for (int it = 0; it < 2; it++) {
            int idx = tid + it * 256;        // (n, k4): 128 x 4
            int n = idx >> 2, k4 = idx & 3;
            cpa16(bt + (unsigned)(n * 16 + k4 * 4) * 4u,
                  &g_wqkvp[(size_t)(n0 + n) * CC + kk0 + k4 * 4]);
        }
    };

    float acc[4][4][4];
    #pragma unroll
    for (int i = 0; i < 4; i++)
        #pragma unroll
        for (int j = 0; j < 4; j++)
            #pragma unroll
            for (int r = 0; r < 4; r++) acc[i][j][r] = 0.f;

    issue_stage(0, 0);  CPA_COMMIT();
    issue_stage(16, 1); CPA_COMMIT();
    issue_stage(32, 2); CPA_COMMIT();

    for (int kt = 0; kt < 32; kt++) {
        CPA_WAIT(2);
        __syncthreads();
        if (kt + 3 < 32) issue_stage((kt + 3) * 16, (kt + 3) & 3);
        CPA_COMMIT();

        const unsigned* As_ = smg + (kt & 3) * QSTG;
        const unsigned* Bs_ = As_ + QA_W;

        uint4 bq[4];
        #pragma unroll
        for (int nt = 0; nt < 4; nt++)
            bq[nt] = *(const uint4*)&Bs_[(wn + nt * 8 + qr) * 16 + 4 * qc];

        #pragma unroll
        for (int ks = 0; ks < 2; ks++) {
            int ksq = ks * 8 + qc;
            unsigned af[4][4];
            #pragma unroll
            for (int mt = 0; mt < 4; mt++) {
                int mb = wm + mt * 16;
                af[mt][0] = As_[ksq * 136 + mb + qr];
                af[mt][1] = As_[ksq * 136 + mb + qr + 8];
                af[mt][2] = As_[(ksq + 4) * 136 + mb + qr];
                af[mt][3] = As_[(ksq + 4) * 136 + mb + qr + 8];
            }
            #pragma unroll
            for (int mt = 0; mt < 4; mt++)
                #pragma unroll
                for (int nt = 0; nt < 4; nt++)
                    mma_tf32(acc[mt][nt], af[mt],
                             ks ? bq[nt].z : bq[nt].x,
                             ks ? bq[nt].w : bq[nt].y);
        }
    }

    // epilogue: LN affine fold; K -> g_ktb (bf16 pairs); V -> g_vtb (bf16)
    const bool kreg = (n0 >= CC && n0 < 2 * CC);
    const bool vreg = (n0 >= 2 * CC);
    const int tpo0 = (qr >> 1) * 4 + (qr & 1);   // pi(qr), tokens 0-7
    const int tpo1 = tpo0 + 2;                   // pi(qr+8)
    #pragma unroll
    for (int mt = 0; mt < 4; mt++) {
        int ml0 = wm + mt * 16 + qr;
        int ml1 = ml0 + 8;
        float s0 = g_rs[m0 + ml0], u0 = g_mu[m0 + ml0];
        float s1 = g_rs[m0 + ml1], u1 = g_mu[m0 + ml1];
        #pragma unroll
        for (int nt = 0; nt < 4; nt++) {
            int n = n0 + wn + nt * 8 + 2 * qc;
            float cs0 = __ldg(&g_cs[n]),     be0 = __ldg(&g_be[n]);
            float cs1 = __ldg(&g_cs[n + 1]), be1 = __ldg(&g_be[n + 1]);
            float v00 = s0 * (acc[mt][nt][0] - u0 * cs0) + be0;
            float v01 = s0 * (acc[mt][nt][1] - u0 * cs1) + be1;
            float v10 = s1 * (acc[mt][nt][2] - u1 * cs0) + be0;
            float v11 = s1 * (acc[mt][nt][3] - u1 * cs1) + be1;
            if (vreg) {
                int hh = (n - 2 * CC) >> 6;
                int dh = (n - 2 * CC) & 63;
                int tq = l0 + wm + mt * 16;            // 16-aligned token base
                size_t vb = ((size_t)(b * HH + hh) * DHD + dh) * LL;
                g_vtb[vb + tq + tpo0]      = __float2bfloat16(v00);
                g_vtb[vb + LL + tq + tpo0] = __float2bfloat16(v01);
                g_vtb[vb + tq + tpo1]      = __float2bfloat16(v10);
                g_vtb[vb + LL + tq + tpo1] = __float2bfloat16(v11);
            } else if (kreg) {
                int dh = (n - CC) & 63;                // even
                int hh = (n - CC) >> 6;
                int np = PPERM(dh);                    // even; pair -> np, np+1
                int tok0 = l0 + ml0;
                int tok1 = l0 + ml1;
                size_t kbase = ((size_t)(b * HH + hh) * LL);
                *(unsigned*)&g_ktb[(kbase + tok0) * DHD + np] = packbf(v01, v00);
                *(unsigned*)&g_ktb[(kbase + tok1) * DHD + np] = packbf(v11, v10);
            } else {
                *(float2*)&g_qkv[(size_t)(m0 + ml0) * N_QKV + n] = make_float2(v00, v01);
                *(float2*)&g_qkv[(size_t)(m0 + ml1) * N_QKV + n] = make_float2(v10, v11);
            }
        }
    }
}

// ---------------------------------------------------------------------------
// Kernel 5: proj GEMM + bias + residual (unchanged).
// ---------------------------------------------------------------------------
#define PA_W 2048
#define PB_W 2048
#define PSTG (PA_W + PB_W)   // 4096
#define PSMEM (PSTG * 4 * 4) // 65536 B

__global__ __launch_bounds__(256, 2) void proj_gemm(
    const float* __restrict__ bias,
    const float* __restrict__ xres,
    float* __restrict__ Cout)
{
    extern __shared__ unsigned smg[];
    const int m0 = blockIdx.x * 128;
    const int n0 = blockIdx.y * 128;
    const int b = m0 >> 11;
    const int l0 = m0 & (LL - 1);

    const int tid = threadIdx.x;
    const int warp = tid >> 5;
    const int lane = tid & 31;
    const int qr = lane >> 2;
    const int qc = lane & 3;
    const int wm = (warp >> 2) * 64;
    const int wn = (warp & 3) * 32;

    unsigned sbase = (unsigned)__cvta_generic_to_shared(smg);

    auto issue_stage = [&](int kk0, int s) {
        unsigned st = sbase + (unsigned)(s * PSTG) * 4u;
        #pragma unroll
        for (int it = 0; it < 2; it++) {
            int idx = tid + it * 256;
            int m = idx >> 2, k4 = idx & 3;
            cpa16(st + (unsigned)(m * 16 + k4 * 4) * 4u,
                  &g_o[(size_t)(m0 + m) * CC + kk0 + k4 * 4]);
        }
        unsigned bt = st + (unsigned)PA_W * 4u;
        #pragma unroll
        for (int it = 0; it < 2; it++) {
            int idx = tid + it * 256;
            int n = idx >> 2, k4 = idx & 3;
            cpa16(bt + (unsigned)(n * 16 + k4 * 4) * 4u,
                  &g_wprojp[(size_t)(n0 + n) * CC + kk0 + k4 * 4]);
        }
    };

    float acc[4][4][4];
    #pragma unroll
    for (int i = 0; i < 4; i++)
        #pragma unroll
        for (int j = 0; j < 4; j++)
            #pragma unroll
            for (int r = 0; r < 4; r++) acc[i][j][r] = 0.f;

    issue_stage(0, 0);  CPA_COMMIT();
    issue_stage(16, 1); CPA_COMMIT();
    issue_stage(32, 2); CPA_COMMIT();

    for (int kt = 0; kt < 32; kt++) {
        CPA_WAIT(2);
        __syncthreads();
        if (kt + 3 < 32) issue_stage((kt + 3) * 16, (kt + 3) & 3);
        CPA_COMMIT();

        const unsigned* As_ = smg + (kt & 3) * PSTG;
        const unsigned* Bs_ = As_ + PA_W;

        uint4 bq[4];
        #pragma unroll
        for (int nt = 0; nt < 4; nt++)
            bq[nt] = *(const uint4*)&Bs_[(wn + nt * 8 + qr) * 16 + 4 * qc];

        #pragma unroll
        for (int mt = 0; mt < 4; mt++) {
            int mb = wm + mt * 16;
            uint4 a0 = *(const uint4*)&As_[(mb + qr) * 16 + 4 * qc];
            uint4 a1 = *(const uint4*)&As_[(mb + qr + 8) * 16 + 4 * qc];
            unsigned af0[4] = {a0.x, a1.x, a0.y, a1.y};
            unsigned af1[4] = {a0.z, a1.z, a0.w, a1.w};
            #pragma unroll
            for (int nt = 0; nt < 4; nt++) {
                mma_tf32(acc[mt][nt], af0, bq[nt].x, bq[nt].y);
                mma_tf32(acc[mt][nt], af1, bq[nt].z, bq[nt].w);
            }
        }
    }

    #pragma unroll
    for (int mt = 0; mt < 4; mt++) {
        #pragma unroll
        for (int nt = 0; nt < 4; nt++) {
            int n = n0 + wn + nt * 8 + 2 * qc;
            float b0v = __ldg(&bias[n]);
            float b1v = __ldg(&bias[n + 1]);
            int ml0 = wm + mt * 16 + qr;
            size_t a00 = ((size_t)(b * CC + n)) * LL + l0 + ml0;
            size_t a01 = ((size_t)(b * CC + n + 1)) * LL + l0 + ml0;
            Cout[a00]     = acc[mt][nt][0] + b0v + xres[a00];
            Cout[a01]     = acc[mt][nt][1] + b1v + xres[a01];
            Cout[a00 + 8] = acc[mt][nt][2] + b0v + xres[a00 + 8];
            Cout[a01 + 8] = acc[mt][nt][3] + b1v + xres[a01 + 8];
        }
    }
}

// ---------------------------------------------------------------------------
// Kernel 4: flash attention, all-bf16 MMA. 4 warps/CTA, 4 CTAs/SM.
// K AND V double-buffered -> ONE __syncthreads per tile; both prefetched
// at tile top (no load serialized behind S).
// smem (words): K0 2560 @0, K1 @2560, V0 @5120, V1 @7680. 40960 B.
// ---------------------------------------------------------------------------
#define KSTB 80              // bf16 units per K row
#define VTSTB 80             // bf16 units per Vt row
#define AT_K0W 0
#define AT_K1W 2560
#define AT_V0W 5120
#define AT_V1W 7680
#define AT_SMEM_BYTES (10240 * 4)
#define NT (LL / 64)

__global__ __launch_bounds__(128, 4) void attn_mma()
{
    extern __shared__ unsigned sma[];

    const int q0 = blockIdx.x * 64;
    const int h = blockIdx.y;
    const int b = blockIdx.z;

    const int tid = threadIdx.x;
    const int warp = tid >> 5;
    const int lane = tid & 31;
    const int qr = lane >> 2;
    const int qc = lane & 3;
    const int wrow = warp * 16;

    unsigned sbase = (unsigned)__cvta_generic_to_shared(sma);

    const __nv_bfloat16* kb = g_ktb + (size_t)(b * HH + h) * LL * DHD;
    const __nv_bfloat16* vt = g_vtb + (size_t)(b * HH + h) * DHD * LL;

    auto load_K = [&](int kt) {
        unsigned kd = sbase + (unsigned)((kt & 1) ? AT_K1W : AT_K0W) * 4u;
        #pragma unroll
        for (int it = 0; it < 4; it++) {
            int idx = tid + it * 128;      // (j, c8): 64 x 8 chunks of 16B
            int j = idx >> 3, c8 = idx & 7;
            cpa16(kd + (unsigned)(j * KSTB * 2 + c8 * 16),
                  kb + (size_t)(kt * 64 + j) * DHD + c8 * 8);
        }
    };
    auto load_V = [&](int kt) {
        unsigned vd = sbase + (unsigned)((kt & 1) ? AT_V1W : AT_V0W) * 4u;
        #pragma unroll
        for (int it = 0; it < 4; it++) {
            int idx = tid + it * 128;      // (dh, c8): 64 x 8 chunks of 16B
            int dh = idx >> 3, c8 = idx & 7;
            cpa16(vd + (unsigned)(dh * VTSTB * 2 + c8 * 16),
                  vt + (size_t)dh * LL + kt * 64 + c8 * 8);
        }
    };

    load_K(0);
    load_V(0);
    CPA_COMMIT();

    // Q fragments: bf16x2 packed, scaled by SCALE*log2e (Q region natural fp32)
    const float* qptr = g_qkv + ((size_t)(b * LL + q0 + wrow)) * N_QKV + h * DHD;
    const float qsc = SCALEV * LOG2E;
    unsigned qa[4][4];
    #pragma unroll
    for (int g = 0; g < 4; g++) {
        int k0 = g * 16 + 2 * qc;
        qa[g][0] = packbf(qptr[(size_t)qr * N_QKV + k0 + 1] * qsc,
                          qptr[(size_t)qr * N_QKV + k0] * qsc);
        qa[g][1] = packbf(qptr[(size_t)(qr + 8) * N_QKV + k0 + 1] * qsc,
                          qptr[(size_t)(qr + 8) * N_QKV + k0] * qsc);
        qa[g][2] = packbf(qptr[(size_t)qr * N_QKV + k0 + 9] * qsc,
                          qptr[(size_t)qr * N_QKV + k0 + 8] * qsc);
        qa[g][3] = packbf(qptr[(size_t)(qr + 8) * N_QKV + k0 + 9] * qsc,
                          qptr[(size_t)(qr + 8) * N_QKV + k0 + 8] * qsc);
    }

    float oacc[8][4];
    #pragma unroll
    for (int nt = 0; nt < 8; nt++)
        #pragma unroll
        for (int r = 0; r < 4; r++) oacc[nt][r] = 0.f;
    float lp0 = 0.f, lp1 = 0.f;

    for (int kt = 0; kt < NT; kt++) {
        CPA_WAIT(0);
        __syncthreads();
        if (kt + 1 < NT) { load_K(kt + 1); load_V(kt + 1); }
        CPA_COMMIT();

        const unsigned short* Ks_ =
            (const unsigned short*)(sma + ((kt & 1) ? AT_K1W : AT_K0W));
        const unsigned short* Vt_ =
            (const unsigned short*)(sma + ((kt & 1) ? AT_V1W : AT_V0W));

        // ---- S = (Q*scale*log2e) K^T : bf16 m16n8k16, LDS.64 K frags ----
        float sacc[8][4];
        #pragma unroll
        for (int nt = 0; nt < 8; nt++) {
            #pragma unroll
            for (int r = 0; r < 4; r++) sacc[nt][r] = 0.f;
            #pragma unroll
            for (int g = 0; g < 4; g++) {
                uint2 kv = *(const uint2*)&Ks_[(nt * 8 + qr) * KSTB + g * 16 + qc * 4];
                mma_bf16(sacc[nt], qa[g], kv.x, kv.y);
            }
        }

        // ---- softmax numerator: exp2 directly ----
        #pragma unroll
        for (int nt = 0; nt < 8; nt++) {
            sacc[nt][0] = exp2f(sacc[nt][0]);
            sacc[nt][1] = exp2f(sacc[nt][1]);
            sacc[nt][2] = exp2f(sacc[nt][2]);
            sacc[nt][3] = exp2f(sacc[nt][3]);
            lp0 += sacc[nt][0] + sacc[nt][1];
            lp1 += sacc[nt][2] + sacc[nt][3];
        }

        // ---- O += P V : bf16 m16n8k16, LDS.64 Vt fragments ----
        #pragma unroll
        for (int g = 0; g < 4; g++) {     // 16-key groups
            unsigned pa[4];
            pa[0] = packbf(sacc[2 * g][1],     sacc[2 * g][0]);
            pa[1] = packbf(sacc[2 * g][3],     sacc[2 * g][2]);
            pa[2] = packbf(sacc[2 * g + 1][1], sacc[2 * g + 1][0]);
            pa[3] = packbf(sacc[2 * g + 1][3], sacc[2 * g + 1][2]);
            #pragma unroll
            for (int nt = 0; nt < 8; nt++) {
                uint2 bb = *(const uint2*)&Vt_[(nt * 8 + qr) * VTSTB + g * 16 + qc * 4];
                mma_bf16(oacc[nt], pa, bb.x, bb.y);
            }
        }
    }

    // final sum reduction, normalize, store (k-permuted cols)
    lp0 += __shfl_xor_sync(0xffffffffu, lp0, 1);
    lp0 += __shfl_xor_sync(0xffffffffu, lp0, 2);
    lp1 += __shfl_xor_sync(0xffffffffu, lp1, 1);
    lp1 += __shfl_xor_sync(0xffffffffu, lp1, 2);
    float inv0 = 1.0f / lp0;
    float inv1 = 1.0f / lp1;

    size_t row0 = ((size_t)(b * LL + q0 + wrow + qr)) * CC;
    size_t row1 = row0 + (size_t)8 * CC;
    #pragma unroll
    for (int nt = 0; nt < 8; nt++) {
        int c0 = h * DHD + nt * 8 + 2 * qc;
        int cp0 = (c0 & ~15) | PERM16(c0 & 15);
        int cp1 = cp0 + 4;   // perm(c0+1) = perm(c0)+4 for even c0
        g_o[row0 + cp0] = oacc[nt][0] * inv0;
        g_o[row0 + cp1] = oacc[nt][1] * inv0;
        g_o[row1 + cp0] = oacc[nt][2] * inv1;
        g_o[row1 + cp1] = oacc[nt][3] * inv1;
    }
}

// ---------------------------------------------------------------------------
extern "C" void kernel_launch(void* const* d_in, const int* in_sizes, int n_in,
                              void* d_out, int out_size)
{
    const float* x        = (const float*)d_in[0];
    const float* ln_gamma = (const float*)d_in[1];
    const float* ln_beta  = (const float*)d_in[2];
    const float* w_qkv    = (const float*)d_in[3];
    const float* b_qkv    = (const float*)d_in[4];
    const float* w_proj   = (const float*)d_in[5];
    const float* b_proj   = (const float*)d_in[6];
    float* out = (float*)d_out;

    static int attrs_set = 0;
    if (!attrs_set) {
        cudaFuncSetAttribute(attn_mma, cudaFuncAttributeMaxDynamicSharedMemorySize, AT_SMEM_BYTES);
        cudaFuncSetAttribute(qkv_gemm, cudaFuncAttributeMaxDynamicSharedMemorySize, QSMEM);
        cudaFuncSetAttribute(proj_gemm, cudaFuncAttributeMaxDynamicSharedMemorySize, PSMEM);
        attrs_set = 1;
    }

    // 1. LN stats (mu, rstd per row)
    ln_stats<<<dim3(LL / 64, BB), 256>>>(x);

    // 2. Weight prep (gamma-fold + k-permutation + colsums)
    prep_kernel<<<N_QKV + CC, 128>>>(w_qkv, b_qkv, ln_gamma, ln_beta, w_proj);

    // 3. QKV GEMM (AMAJ x loads; LN fused; K -> g_ktb; V -> g_vtb)
    qkv_gemm<<<dim3(BLT / 128, N_QKV / 128), 256, QSMEM>>>(x);

    // 4. Attention (bf16 S + bf16 PV, K+V double-buffered, 1 sync/tile)
    attn_mma<<<dim3(LL / 64, HH, BB), 128, AT_SMEM_BYTES>>>();

    // 5. Proj GEMM + bias + residual
    proj_gemm<<<dim3(BLT / 128, CC / 128), 256, PSMEM>>>(b_proj, x, out);
}